// round 13
// baseline (speedup 1.0000x reference)
#include <cuda_runtime.h>
#include <math.h>

#define BB 2
#define SS 1024
#define TT 1024
#define DS 128
#define DT 64
#define H 64
#define LN_EPS 1e-5f

#define TILE_T 8
#define CH 32
#define USTRIDE 68   // floats; 272B row stride, 16B-aligned, conflict-free 16B reads
#define TTG 4        // t-rows per transfer block

typedef unsigned long long ull;

__device__ __forceinline__ ull fma2(ull a, ull b, ull c) {
    ull d; asm("fma.rn.f32x2 %0,%1,%2,%3;" : "=l"(d) : "l"(a), "l"(b), "l"(c)); return d;
}
__device__ __forceinline__ ull add2(ull a, ull b) {
    ull d; asm("add.rn.f32x2 %0,%1,%2;" : "=l"(d) : "l"(a), "l"(b)); return d;
}
__device__ __forceinline__ ull pack2(float lo, float hi) {
    ull d; asm("mov.b64 %0,{%1,%2};" : "=l"(d) : "f"(lo), "f"(hi)); return d;
}
__device__ __forceinline__ float2 unpack2(ull v) {
    float2 r; asm("mov.b64 {%0,%1},%2;" : "=f"(r.x), "=f"(r.y) : "l"(v)); return r;
}
__device__ __forceinline__ void cp16(void* smem_dst, const void* gsrc) {
    unsigned sa = (unsigned)__cvta_generic_to_shared(smem_dst);
    asm volatile("cp.async.cg.shared.global [%0], [%1], 16;" :: "r"(sa), "l"(gsrc));
}

// ---------------- scratch ----------------
__device__ float g_s_ad[BB * SS * H];
__device__ float g_u[BB * SS * H];
__device__ float g_t_ad[BB * TT * H];
__device__ float g_a[BB * TT * H];
__device__ float g_sum_u[BB * SS];
__device__ float g_su2[BB * SS];
__device__ float g_sum_a[BB * TT];
__device__ float g_sa2[BB * TT];
__device__ float g_gate[BB * TT];

// constants for score kernel (LDC.128 path)
__constant__ __align__(16) float c_cg[H];
__constant__ __align__(16) float c_cb[H];
__constant__ __align__(16) float c_w[H];
__constant__ float c_simb[1];

// ---------------- adapter body: 64 thr/row, explicit 8-deep LDG batches (MLP=8) ----------------
template <int DIN, bool IS_TARGET>
__device__ __forceinline__ void adapter_body(
    int row, int gid, int j,
    const float* __restrict__ X,
    const float* __restrict__ W1, const float* __restrict__ b1,
    const float* __restrict__ g,  const float* __restrict__ beta,
    const float* __restrict__ W2, const float* __restrict__ b2,
    const float* __restrict__ cWpart, const float* __restrict__ cb,
    float* sx, float* sr, float* sa, float* sred)
{
    const int wid = j >> 5;

    const float4* xrow4 = (const float4*)(X + (size_t)row * DIN);
    if (j < DIN / 4) ((float4*)sx)[j] = xrow4[j];
    __syncthreads();

    // layer 1: 8-deep weight-load batches, 4 FMA chains
    float h0 = 0.f, h1 = 0.f, h2 = 0.f, h3 = 0.f;
#pragma unroll
    for (int k0 = 0; k0 < DIN; k0 += 8) {
        float w0 = W1[(k0 + 0) * H + j];
        float w1 = W1[(k0 + 1) * H + j];
        float w2 = W1[(k0 + 2) * H + j];
        float w3 = W1[(k0 + 3) * H + j];
        float w4 = W1[(k0 + 4) * H + j];
        float w5 = W1[(k0 + 5) * H + j];
        float w6 = W1[(k0 + 6) * H + j];
        float w7 = W1[(k0 + 7) * H + j];
        h0 = fmaf(sx[k0 + 0], w0, h0);
        h1 = fmaf(sx[k0 + 1], w1, h1);
        h2 = fmaf(sx[k0 + 2], w2, h2);
        h3 = fmaf(sx[k0 + 3], w3, h3);
        h0 = fmaf(sx[k0 + 4], w4, h0);
        h1 = fmaf(sx[k0 + 5], w5, h1);
        h2 = fmaf(sx[k0 + 6], w6, h2);
        h3 = fmaf(sx[k0 + 7], w7, h3);
    }
    float h = ((h0 + h1) + (h2 + h3)) + b1[j];

    float s1 = h, s2 = h * h;
#pragma unroll
    for (int o = 16; o; o >>= 1) {
        s1 += __shfl_xor_sync(~0u, s1, o);
        s2 += __shfl_xor_sync(~0u, s2, o);
    }
    if ((j & 31) == 0) { sred[wid] = s1; sred[2 + wid] = s2; }
    __syncthreads();
    const float m   = (sred[0] + sred[1]) * (1.f / H);
    const float e2  = (sred[2] + sred[3]) * (1.f / H);
    const float inv = rsqrtf(e2 - m * m + LN_EPS);
    float r = (h - m) * inv * g[j] + beta[j];
    r = fmaxf(r, 0.f);
    __syncthreads();
    sr[j] = r;
    __syncthreads();

    // layer 2: 8-deep batches
    float a0 = 0.f, a1 = 0.f, a2v = 0.f, a3 = 0.f;
#pragma unroll
    for (int k0 = 0; k0 < H; k0 += 8) {
        float w0 = W2[(k0 + 0) * H + j];
        float w1 = W2[(k0 + 1) * H + j];
        float w2 = W2[(k0 + 2) * H + j];
        float w3 = W2[(k0 + 3) * H + j];
        float w4 = W2[(k0 + 4) * H + j];
        float w5 = W2[(k0 + 5) * H + j];
        float w6 = W2[(k0 + 6) * H + j];
        float w7 = W2[(k0 + 7) * H + j];
        a0  = fmaf(sr[k0 + 0], w0, a0);
        a1  = fmaf(sr[k0 + 1], w1, a1);
        a2v = fmaf(sr[k0 + 2], w2, a2v);
        a3  = fmaf(sr[k0 + 3], w3, a3);
        a0  = fmaf(sr[k0 + 4], w4, a0);
        a1  = fmaf(sr[k0 + 5], w5, a1);
        a2v = fmaf(sr[k0 + 6], w6, a2v);
        a3  = fmaf(sr[k0 + 7], w7, a3);
    }
    float ad = ((a0 + a1) + (a2v + a3)) + b2[j];

    if (IS_TARGET) {
        g_t_ad[(size_t)row * H + j] = ad;
        float s = ad;
#pragma unroll
        for (int o = 16; o; o >>= 1) s += __shfl_xor_sync(~0u, s, o);
        if ((j & 31) == 0) sred[wid] = s;
    } else {
        g_s_ad[(size_t)row * H + j] = ad;
    }
    sa[j] = ad;
    __syncthreads();

    if (IS_TARGET && j == 0) {
        float mt = (sred[0] + sred[1]) * (1.f / H);
        g_gate[row] = 1.f / (1.f + __expf(-mt));
    }

    // projection: 8-deep batches
    float p0 = IS_TARGET ? cb[j] : 0.f, p1k = 0.f, p2k = 0.f, p3k = 0.f;
#pragma unroll
    for (int k0 = 0; k0 < H; k0 += 8) {
        float w0 = cWpart[(k0 + 0) * H + j];
        float w1 = cWpart[(k0 + 1) * H + j];
        float w2 = cWpart[(k0 + 2) * H + j];
        float w3 = cWpart[(k0 + 3) * H + j];
        float w4 = cWpart[(k0 + 4) * H + j];
        float w5 = cWpart[(k0 + 5) * H + j];
        float w6 = cWpart[(k0 + 6) * H + j];
        float w7 = cWpart[(k0 + 7) * H + j];
        p0  = fmaf(sa[k0 + 0], w0, p0);
        p1k = fmaf(sa[k0 + 1], w1, p1k);
        p2k = fmaf(sa[k0 + 2], w2, p2k);
        p3k = fmaf(sa[k0 + 3], w3, p3k);
        p0  = fmaf(sa[k0 + 4], w4, p0);
        p1k = fmaf(sa[k0 + 5], w5, p1k);
        p2k = fmaf(sa[k0 + 6], w6, p2k);
        p3k = fmaf(sa[k0 + 7], w7, p3k);
    }
    float p = ((p0 + p1k) + (p2k + p3k));

    if (IS_TARGET) g_a[(size_t)row * H + j] = p;
    else           g_u[(size_t)row * H + j] = p;

    float q1 = p, q2 = p * p;
#pragma unroll
    for (int o = 16; o; o >>= 1) {
        q1 += __shfl_xor_sync(~0u, q1, o);
        q2 += __shfl_xor_sync(~0u, q2, o);
    }
    __syncthreads();
    if ((j & 31) == 0) { sred[wid] = q1; sred[2 + wid] = q2; }
    __syncthreads();
    if (j == 0) {
        if (IS_TARGET) { g_sum_a[row] = sred[0] + sred[1]; g_sa2[row] = sred[2] + sred[3]; }
        else           { g_sum_u[row] = sred[0] + sred[1]; g_su2[row] = sred[2] + sred[3]; }
    }
}

// ---------------- fused adapters: blocks [0,512) source, [512,1024) target ----------------
__global__ __launch_bounds__(256)
void adapters_fused(const float* __restrict__ src, const float* __restrict__ tgt,
                    const float* __restrict__ sW1, const float* __restrict__ sb1,
                    const float* __restrict__ sg,  const float* __restrict__ sbeta,
                    const float* __restrict__ sW2, const float* __restrict__ sb2,
                    const float* __restrict__ tW1, const float* __restrict__ tb1,
                    const float* __restrict__ tgam, const float* __restrict__ tbeta,
                    const float* __restrict__ tW2, const float* __restrict__ tb2,
                    const float* __restrict__ cW,  const float* __restrict__ cb)
{
    __shared__ float sh_x[4][DS];
    __shared__ float sh_r[4][H];
    __shared__ float sh_ad[4][H];
    __shared__ float sh_red[4][4];

    const int gid = threadIdx.x >> 6;
    const int j = threadIdx.x & 63;
    const int SRC_BLOCKS = BB * SS / 4;

    if (blockIdx.x < SRC_BLOCKS) {
        int row = blockIdx.x * 4 + gid;
        adapter_body<DS, false>(row, gid, j, src, sW1, sb1, sg, sbeta, sW2, sb2,
                                cW + H * H, nullptr,
                                sh_x[gid], sh_r[gid], sh_ad[gid], sh_red[gid]);
    } else {
        int row = (blockIdx.x - SRC_BLOCKS) * 4 + gid;
        adapter_body<DT, true>(row, gid, j, tgt, tW1, tb1, tgam, tbeta, tW2, tb2,
                               cW, cb,
                               sh_x[gid], sh_r[gid], sh_ad[gid], sh_red[gid]);
    }
}

// ---------------- score kernel: CH=32, 3-buffer cp.async ring, ONE barrier per chunk ----
__global__ __launch_bounds__(256, 2)
void score_kernel(float* __restrict__ out_scores)
{
    __shared__ __align__(16) float u_sh[3][CH * USTRIDE];
    __shared__ __align__(16) float a_sh[TILE_T][H];

    const int tid = threadIdx.x;
    const int lane = tid & 31;
    const int w = tid >> 5;
    const int tglob = blockIdx.x * TILE_T + w;
    const int b = tglob >> 10;
    const int srow0 = b << 10;

    ((float2*)a_sh[w])[lane] = ((const float2*)(g_a + (size_t)tglob * H))[lane];

    const float suma = g_sum_a[tglob];
    const float sqa  = g_sa2[tglob];
    const float simb0 = c_simb[0];

    // prologue: stage chunk 0 into buf 0
    {
        const float4* src = (const float4*)(g_u + (size_t)srow0 * H);
#pragma unroll
        for (int rep = 0; rep < 2; rep++) {
            int f = tid + rep * 256;
            int r = f >> 4, q = f & 15;
            cp16(&u_sh[0][r * USTRIDE + q * 4], src + f);
        }
        asm volatile("cp.async.commit_group;");
    }

    float* srow_out = out_scores + (size_t)tglob * SS;

    int buf = 0;
    for (int c = 0; c < SS / CH; c++) {
        if (c < SS / CH - 1) {
            const float4* src = (const float4*)(g_u + (size_t)(srow0 + (c + 1) * CH) * H);
            float* dst = u_sh[(buf + 1) % 3];
#pragma unroll
            for (int rep = 0; rep < 2; rep++) {
                int f = tid + rep * 256;
                int r = f >> 4, q = f & 15;
                cp16(&dst[r * USTRIDE + q * 4], src + f);
            }
            asm volatile("cp.async.commit_group;");
            asm volatile("cp.async.wait_group 1;");
        } else {
            asm volatile("cp.async.wait_group 0;");
        }
        __syncthreads();

        const ulonglong2* up2 = (const ulonglong2*)&u_sh[buf][lane * USTRIDE];
        ull u2[H / 2];
#pragma unroll
        for (int i = 0; i < H / 4; i++) {
            ulonglong2 v = up2[i];
            u2[2 * i] = v.x; u2[2 * i + 1] = v.y;
        }

        const int sidx = srow0 + c * CH + lane;
        const float su  = g_sum_u[sidx];
        const float squ = g_su2[sidx];

        const ulonglong2* ap2 = (const ulonglong2*)a_sh[w];

        ull d0 = 0ull, d1 = 0ull, d2 = 0ull, d3 = 0ull;
#pragma unroll
        for (int i = 0; i < H / 4; i += 2) {
            ulonglong2 aa = ap2[i];
            ulonglong2 ab = ap2[i + 1];
            d0 = fma2(aa.x, u2[2 * i],     d0);
            d1 = fma2(aa.y, u2[2 * i + 1], d1);
            d2 = fma2(ab.x, u2[2 * i + 2], d2);
            d3 = fma2(ab.y, u2[2 * i + 3], d3);
        }
        float2 f0 = unpack2(d0), f1 = unpack2(d1), f2 = unpack2(d2), f3 = unpack2(d3);
        const float dot = ((f0.x + f0.y) + (f1.x + f1.y)) + ((f2.x + f2.y) + (f3.x + f3.y));

        const float m   = (suma + su) * (1.f / H);
        const float e2  = (sqa + 2.f * dot + squ) * (1.f / H);
        const float inv = rsqrtf(e2 - m * m + LN_EPS);
        const float nm  = -m * inv;
        const ull inv2 = pack2(inv, inv);
        const ull nm2  = pack2(nm, nm);

        ull acca = 0ull, accb = 0ull;
#pragma unroll
        for (int i = 0; i < H / 4; i++) {
            ulonglong2 aa  = ap2[i];
            ulonglong2 kcg = *(const ulonglong2*)&c_cg[4 * i];
            ulonglong2 kcb = *(const ulonglong2*)&c_cb[4 * i];
            ulonglong2 kw  = *(const ulonglong2*)&c_w[4 * i];
            ull p0 = add2(aa.x, u2[2 * i]);
            ull p1 = add2(aa.y, u2[2 * i + 1]);
            ull z0 = fma2(p0, inv2, nm2);
            ull z1 = fma2(p1, inv2, nm2);
            ull y0 = fma2(z0, kcg.x, kcb.x);
            ull y1 = fma2(z1, kcg.y, kcb.y);
            float2 ya = unpack2(y0), yb = unpack2(y1);
            ya.x = fmaxf(ya.x, 0.f); ya.y = fmaxf(ya.y, 0.f);
            yb.x = fmaxf(yb.x, 0.f); yb.y = fmaxf(yb.y, 0.f);
            acca = fma2(pack2(ya.x, ya.y), kw.x, acca);
            accb = fma2(pack2(yb.x, yb.y), kw.y, accb);
        }
        float2 sa2 = unpack2(acca), sb2 = unpack2(accb);
        const float acc = (sa2.x + sa2.y) + (sb2.x + sb2.y);
        const float score = 1.f / (1.f + __expf(-(acc + simb0)));
        srow_out[c * CH + lane] = score;

        buf = (buf + 1) % 3;
    }
}

// ---------------- transfer: 256 thr / 8 warps, TTG=4; e2/red smem UNION ----------------
__global__ __launch_bounds__(256)
void transfer_kernel(const float* __restrict__ scores, float* __restrict__ out_adapted)
{
    __shared__ __align__(16) ull sh[8][32 * TTG];   // 8KB; e2 view phase1, red view phase2
    __shared__ float sums_sh[8][TTG];

    const int tid = threadIdx.x;
    const int w = tid >> 5, lane = tid & 31;
    const int tbase = blockIdx.x * TTG;
    const int b = tbase >> 10;
    const int srow0 = b << 10;

    ull acc2[TTG];
    float se[TTG];
#pragma unroll
    for (int t = 0; t < TTG; t++) { acc2[t] = 0ull; se[t] = 0.f; }

    for (int c = 0; c < 4; c++) {
        const int sloc0 = w * 128 + c * 32;

#pragma unroll
        for (int t = 0; t < TTG; t++) {
            float e = __expf(scores[(size_t)(tbase + t) * SS + sloc0 + lane]);
            se[t] += e;
            sh[w][lane * TTG + t] = pack2(e, e);
        }
        __syncwarp();

#pragma unroll 4
        for (int j = 0; j < 32; j += 8) {
            ull v[8];
#pragma unroll
            for (int k = 0; k < 8; k++)
                v[k] = *(const ull*)(g_s_ad + (size_t)(srow0 + sloc0 + j + k) * H + 2 * lane);
#pragma unroll
            for (int k = 0; k < 8; k++) {
                const ulonglong2* ep = (const ulonglong2*)&sh[w][(j + k) * TTG];
                ulonglong2 e01 = ep[0], e23 = ep[1];
                acc2[0] = fma2(v[k], e01.x, acc2[0]);
                acc2[1] = fma2(v[k], e01.y, acc2[1]);
                acc2[2] = fma2(v[k], e23.x, acc2[2]);
                acc2[3] = fma2(v[k], e23.y, acc2[3]);
            }
        }
        __syncwarp();
    }

#pragma unroll
    for (int t = 0; t < TTG; t++) {
        float s = se[t];
#pragma unroll
        for (int o = 16; o; o >>= 1) s += __shfl_xor_sync(~0u, s, o);
        if (lane == 0) sums_sh[w][t] = s;
    }

    float* red = (float*)sh;
#pragma unroll
    for (int t = 0; t < TTG; t++)
        *(ull*)&red[(w * TTG + t) * H + 2 * lane] = acc2[t];
    __syncthreads();

    const int t = tid >> 6;
    const int hh = tid & 63;
    float s = 0.f;
#pragma unroll
    for (int ww = 0; ww < 8; ww++) s += red[(ww * TTG + t) * H + hh];
    float sumexp = 0.f;
#pragma unroll
    for (int ww = 0; ww < 8; ww++) sumexp += sums_sh[ww][t];

    const int tg = tbase + t;
    const float rs = 1.f / sumexp;
    const float gt = g_gate[tg];
    const float ta = g_t_ad[(size_t)tg * H + hh];
    out_adapted[(size_t)tg * H + hh] = ta * (1.f - gt) + s * rs * gt;
}

// ---------------- launch ----------------
extern "C" void kernel_launch(void* const* d_in, const int* in_sizes, int n_in,
                              void* d_out, int out_size)
{
    (void)in_sizes; (void)n_in; (void)out_size;
    const float* src   = (const float*)d_in[0];
    const float* tgt   = (const float*)d_in[1];
    const float* sW1   = (const float*)d_in[2];
    const float* sb1   = (const float*)d_in[3];
    const float* sg    = (const float*)d_in[4];
    const float* sbeta = (const float*)d_in[5];
    const float* sW2   = (const float*)d_in[6];
    const float* sb2   = (const float*)d_in[7];
    const float* tW1   = (const float*)d_in[8];
    const float* tb1   = (const float*)d_in[9];
    const float* tg    = (const float*)d_in[10];
    const float* tbeta = (const float*)d_in[11];
    const float* tW2   = (const float*)d_in[12];
    const float* tb2   = (const float*)d_in[13];
    const float* cW    = (const float*)d_in[14];
    const float* cb    = (const float*)d_in[15];
    const float* cg    = (const float*)d_in[16];
    const float* cbeta = (const float*)d_in[17];
    const float* simW  = (const float*)d_in[18];
    const float* simb  = (const float*)d_in[19];

    float* out_adapted = (float*)d_out;                      // (B,T,H)
    float* out_scores  = out_adapted + (size_t)BB * TT * H;  // (B,T,S)

    cudaMemcpyToSymbolAsync(c_cg,   cg,    H * sizeof(float), 0, cudaMemcpyDeviceToDevice, 0);
    cudaMemcpyToSymbolAsync(c_cb,   cbeta, H * sizeof(float), 0, cudaMemcpyDeviceToDevice, 0);
    cudaMemcpyToSymbolAsync(c_w,    simW,  H * sizeof(float), 0, cudaMemcpyDeviceToDevice, 0);
    cudaMemcpyToSymbolAsync(c_simb, simb,  sizeof(float),     0, cudaMemcpyDeviceToDevice, 0);

    adapters_fused<<<BB * SS / 4 + BB * TT / 4, 256>>>(src, tgt,
                                                       sW1, sb1, sg, sbeta, sW2, sb2,
                                                       tW1, tb1, tg, tbeta, tW2, tb2,
                                                       cW, cb);
    score_kernel<<<(BB * TT) / TILE_T, 256>>>(out_scores);
    transfer_kernel<<<(BB * TT) / TTG, 256>>>(out_scores, out_adapted);
}

// round 15
// speedup vs baseline: 1.0202x; 1.0202x over previous
#include <cuda_runtime.h>
#include <math.h>

#define BB 2
#define SS 1024
#define TT 1024
#define DS 128
#define DT 64
#define H 64
#define LN_EPS 1e-5f

#define TILE_T 8
#define CH 32
#define USTRIDE 68   // floats; 272B row stride, 16B-aligned, conflict-free 16B reads
#define TTG 8        // t-rows per transfer block (halves s_ad L2 traffic vs 4)

typedef unsigned long long ull;

__device__ __forceinline__ ull fma2(ull a, ull b, ull c) {
    ull d; asm("fma.rn.f32x2 %0,%1,%2,%3;" : "=l"(d) : "l"(a), "l"(b), "l"(c)); return d;
}
__device__ __forceinline__ ull add2(ull a, ull b) {
    ull d; asm("add.rn.f32x2 %0,%1,%2;" : "=l"(d) : "l"(a), "l"(b)); return d;
}
__device__ __forceinline__ ull pack2(float lo, float hi) {
    ull d; asm("mov.b64 %0,{%1,%2};" : "=l"(d) : "f"(lo), "f"(hi)); return d;
}
__device__ __forceinline__ float2 unpack2(ull v) {
    float2 r; asm("mov.b64 {%0,%1},%2;" : "=f"(r.x), "=f"(r.y) : "l"(v)); return r;
}
__device__ __forceinline__ void cp16(void* smem_dst, const void* gsrc) {
    unsigned sa = (unsigned)__cvta_generic_to_shared(smem_dst);
    asm volatile("cp.async.cg.shared.global [%0], [%1], 16;" :: "r"(sa), "l"(gsrc));
}

// ---------------- scratch ----------------
__device__ float g_s_ad[BB * SS * H];
__device__ float g_u[BB * SS * H];
__device__ float g_t_ad[BB * TT * H];
__device__ float g_a[BB * TT * H];
__device__ float g_sum_u[BB * SS];
__device__ float g_su2[BB * SS];
__device__ float g_sum_a[BB * TT];
__device__ float g_sa2[BB * TT];
__device__ float g_gate[BB * TT];

// constants for score kernel (LDC.128 path)
__constant__ __align__(16) float c_cg[H];
__constant__ __align__(16) float c_cb[H];
__constant__ __align__(16) float c_w[H];
__constant__ float c_simb[1];

// ---------------- adapter body (proven: 64 threads/row, 4 rows/block) ----------------
template <int DIN, bool IS_TARGET>
__device__ __forceinline__ void adapter_body(
    int row, int gid, int j,
    const float* __restrict__ X,
    const float* __restrict__ W1, const float* __restrict__ b1,
    const float* __restrict__ g,  const float* __restrict__ beta,
    const float* __restrict__ W2, const float* __restrict__ b2,
    const float* __restrict__ cWpart, const float* __restrict__ cb,
    float* sx, float* sr, float* sa, float* sred)
{
    const int wid = j >> 5;

    const float4* xrow4 = (const float4*)(X + (size_t)row * DIN);
    if (j < DIN / 4) ((float4*)sx)[j] = xrow4[j];
    __syncthreads();

    float h0 = 0.f, h1 = 0.f, h2 = 0.f, h3 = 0.f;
#pragma unroll
    for (int k = 0; k < DIN; k += 4) {
        h0 = fmaf(sx[k],     W1[(k)     * H + j], h0);
        h1 = fmaf(sx[k + 1], W1[(k + 1) * H + j], h1);
        h2 = fmaf(sx[k + 2], W1[(k + 2) * H + j], h2);
        h3 = fmaf(sx[k + 3], W1[(k + 3) * H + j], h3);
    }
    float h = ((h0 + h1) + (h2 + h3)) + b1[j];

    float s1 = h, s2 = h * h;
#pragma unroll
    for (int o = 16; o; o >>= 1) {
        s1 += __shfl_xor_sync(~0u, s1, o);
        s2 += __shfl_xor_sync(~0u, s2, o);
    }
    if ((j & 31) == 0) { sred[wid] = s1; sred[2 + wid] = s2; }
    __syncthreads();
    const float m   = (sred[0] + sred[1]) * (1.f / H);
    const float e2  = (sred[2] + sred[3]) * (1.f / H);
    const float inv = rsqrtf(e2 - m * m + LN_EPS);
    float r = (h - m) * inv * g[j] + beta[j];
    r = fmaxf(r, 0.f);
    __syncthreads();
    sr[j] = r;
    __syncthreads();

    float a0 = 0.f, a1 = 0.f, a2v = 0.f, a3 = 0.f;
#pragma unroll
    for (int k = 0; k < H; k += 4) {
        a0  = fmaf(sr[k],     W2[(k)     * H + j], a0);
        a1  = fmaf(sr[k + 1], W2[(k + 1) * H + j], a1);
        a2v = fmaf(sr[k + 2], W2[(k + 2) * H + j], a2v);
        a3  = fmaf(sr[k + 3], W2[(k + 3) * H + j], a3);
    }
    float ad = ((a0 + a1) + (a2v + a3)) + b2[j];

    if (IS_TARGET) {
        g_t_ad[(size_t)row * H + j] = ad;
        float s = ad;
#pragma unroll
        for (int o = 16; o; o >>= 1) s += __shfl_xor_sync(~0u, s, o);
        if ((j & 31) == 0) sred[wid] = s;
    } else {
        g_s_ad[(size_t)row * H + j] = ad;
    }
    sa[j] = ad;
    __syncthreads();

    if (IS_TARGET && j == 0) {
        float mt = (sred[0] + sred[1]) * (1.f / H);
        g_gate[row] = 1.f / (1.f + __expf(-mt));
    }

    float p0 = IS_TARGET ? cb[j] : 0.f, p1k = 0.f, p2k = 0.f, p3k = 0.f;
#pragma unroll
    for (int k = 0; k < H; k += 4) {
        p0  = fmaf(sa[k],     cWpart[(k)     * H + j], p0);
        p1k = fmaf(sa[k + 1], cWpart[(k + 1) * H + j], p1k);
        p2k = fmaf(sa[k + 2], cWpart[(k + 2) * H + j], p2k);
        p3k = fmaf(sa[k + 3], cWpart[(k + 3) * H + j], p3k);
    }
    float p = ((p0 + p1k) + (p2k + p3k));

    if (IS_TARGET) g_a[(size_t)row * H + j] = p;
    else           g_u[(size_t)row * H + j] = p;

    float q1 = p, q2 = p * p;
#pragma unroll
    for (int o = 16; o; o >>= 1) {
        q1 += __shfl_xor_sync(~0u, q1, o);
        q2 += __shfl_xor_sync(~0u, q2, o);
    }
    __syncthreads();
    if ((j & 31) == 0) { sred[wid] = q1; sred[2 + wid] = q2; }
    __syncthreads();
    if (j == 0) {
        if (IS_TARGET) { g_sum_a[row] = sred[0] + sred[1]; g_sa2[row] = sred[2] + sred[3]; }
        else           { g_sum_u[row] = sred[0] + sred[1]; g_su2[row] = sred[2] + sred[3]; }
    }
}

// ---------------- fused adapters: blocks [0,512) source, [512,1024) target ----------------
__global__ __launch_bounds__(256)
void adapters_fused(const float* __restrict__ src, const float* __restrict__ tgt,
                    const float* __restrict__ sW1, const float* __restrict__ sb1,
                    const float* __restrict__ sg,  const float* __restrict__ sbeta,
                    const float* __restrict__ sW2, const float* __restrict__ sb2,
                    const float* __restrict__ tW1, const float* __restrict__ tb1,
                    const float* __restrict__ tgam, const float* __restrict__ tbeta,
                    const float* __restrict__ tW2, const float* __restrict__ tb2,
                    const float* __restrict__ cW,  const float* __restrict__ cb)
{
    __shared__ float sh_x[4][DS];
    __shared__ float sh_r[4][H];
    __shared__ float sh_ad[4][H];
    __shared__ float sh_red[4][4];

    const int gid = threadIdx.x >> 6;
    const int j = threadIdx.x & 63;
    const int SRC_BLOCKS = BB * SS / 4;

    if (blockIdx.x < SRC_BLOCKS) {
        int row = blockIdx.x * 4 + gid;
        adapter_body<DS, false>(row, gid, j, src, sW1, sb1, sg, sbeta, sW2, sb2,
                                cW + H * H, nullptr,
                                sh_x[gid], sh_r[gid], sh_ad[gid], sh_red[gid]);
    } else {
        int row = (blockIdx.x - SRC_BLOCKS) * 4 + gid;
        adapter_body<DT, true>(row, gid, j, tgt, tW1, tb1, tgam, tbeta, tW2, tb2,
                               cW, cb,
                               sh_x[gid], sh_r[gid], sh_ad[gid], sh_red[gid]);
    }
}

// ---------------- score kernel: CH=32, 3-buffer ring (R12 exact, proven) ----------------
__global__ __launch_bounds__(256, 2)
void score_kernel(float* __restrict__ out_scores)
{
    __shared__ __align__(16) float u_sh[3][CH * USTRIDE];
    __shared__ __align__(16) float a_sh[TILE_T][H];

    const int tid = threadIdx.x;
    const int lane = tid & 31;
    const int w = tid >> 5;
    const int tglob = blockIdx.x * TILE_T + w;
    const int b = tglob >> 10;
    const int srow0 = b << 10;

    ((float2*)a_sh[w])[lane] = ((const float2*)(g_a + (size_t)tglob * H))[lane];

    const float suma = g_sum_a[tglob];
    const float sqa  = g_sa2[tglob];
    const float simb0 = c_simb[0];

    {
        const float4* src = (const float4*)(g_u + (size_t)srow0 * H);
#pragma unroll
        for (int rep = 0; rep < 2; rep++) {
            int f = tid + rep * 256;
            int r = f >> 4, q = f & 15;
            cp16(&u_sh[0][r * USTRIDE + q * 4], src + f);
        }
        asm volatile("cp.async.commit_group;");
    }

    float* srow_out = out_scores + (size_t)tglob * SS;

    int buf = 0;
    for (int c = 0; c < SS / CH; c++) {
        if (c < SS / CH - 1) {
            const float4* src = (const float4*)(g_u + (size_t)(srow0 + (c + 1) * CH) * H);
            float* dst = u_sh[(buf + 1) % 3];
#pragma unroll
            for (int rep = 0; rep < 2; rep++) {
                int f = tid + rep * 256;
                int r = f >> 4, q = f & 15;
                cp16(&dst[r * USTRIDE + q * 4], src + f);
            }
            asm volatile("cp.async.commit_group;");
            asm volatile("cp.async.wait_group 1;");
        } else {
            asm volatile("cp.async.wait_group 0;");
        }
        __syncthreads();

        const ulonglong2* up2 = (const ulonglong2*)&u_sh[buf][lane * USTRIDE];
        ull u2[H / 2];
#pragma unroll
        for (int i = 0; i < H / 4; i++) {
            ulonglong2 v = up2[i];
            u2[2 * i] = v.x; u2[2 * i + 1] = v.y;
        }

        const int sidx = srow0 + c * CH + lane;
        const float su  = g_sum_u[sidx];
        const float squ = g_su2[sidx];

        const ulonglong2* ap2 = (const ulonglong2*)a_sh[w];

        ull d0 = 0ull, d1 = 0ull, d2 = 0ull, d3 = 0ull;
#pragma unroll
        for (int i = 0; i < H / 4; i += 2) {
            ulonglong2 aa = ap2[i];
            ulonglong2 ab = ap2[i + 1];
            d0 = fma2(aa.x, u2[2 * i],     d0);
            d1 = fma2(aa.y, u2[2 * i + 1], d1);
            d2 = fma2(ab.x, u2[2 * i + 2], d2);
            d3 = fma2(ab.y, u2[2 * i + 3], d3);
        }
        float2 f0 = unpack2(d0), f1 = unpack2(d1), f2 = unpack2(d2), f3 = unpack2(d3);
        const float dot = ((f0.x + f0.y) + (f1.x + f1.y)) + ((f2.x + f2.y) + (f3.x + f3.y));

        const float m   = (suma + su) * (1.f / H);
        const float e2  = (sqa + 2.f * dot + squ) * (1.f / H);
        const float inv = rsqrtf(e2 - m * m + LN_EPS);
        const float nm  = -m * inv;
        const ull inv2 = pack2(inv, inv);
        const ull nm2  = pack2(nm, nm);

        ull acca = 0ull, accb = 0ull;
#pragma unroll
        for (int i = 0; i < H / 4; i++) {
            ulonglong2 aa  = ap2[i];
            ulonglong2 kcg = *(const ulonglong2*)&c_cg[4 * i];
            ulonglong2 kcb = *(const ulonglong2*)&c_cb[4 * i];
            ulonglong2 kw  = *(const ulonglong2*)&c_w[4 * i];
            ull p0 = add2(aa.x, u2[2 * i]);
            ull p1 = add2(aa.y, u2[2 * i + 1]);
            ull z0 = fma2(p0, inv2, nm2);
            ull z1 = fma2(p1, inv2, nm2);
            ull y0 = fma2(z0, kcg.x, kcb.x);
            ull y1 = fma2(z1, kcg.y, kcb.y);
            float2 ya = unpack2(y0), yb = unpack2(y1);
            ya.x = fmaxf(ya.x, 0.f); ya.y = fmaxf(ya.y, 0.f);
            yb.x = fmaxf(yb.x, 0.f); yb.y = fmaxf(yb.y, 0.f);
            acca = fma2(pack2(ya.x, ya.y), kw.x, acca);
            accb = fma2(pack2(yb.x, yb.y), kw.y, accb);
        }
        float2 sa2 = unpack2(acca), sb2 = unpack2(accb);
        const float acc = (sa2.x + sa2.y) + (sb2.x + sb2.y);
        const float score = 1.f / (1.f + __expf(-(acc + simb0)));
        srow_out[c * CH + lane] = score;

        buf = (buf + 1) % 3;
    }
}

// ---------------- transfer: 256 thr / 8 warps, TTG=8; e2/red smem UNION (16KB) ----------
// Halves s_ad L2 traffic vs TTG=4 (64MB total). Also computes sumexp.
__global__ __launch_bounds__(256)
void transfer_kernel(const float* __restrict__ scores, float* __restrict__ out_adapted)
{
    __shared__ __align__(16) ull sh[8][32 * TTG];   // 16KB; e2 view phase1, red view phase2
    __shared__ float sums_sh[8][TTG];

    const int tid = threadIdx.x;
    const int w = tid >> 5, lane = tid & 31;
    const int tbase = blockIdx.x * TTG;
    const int b = tbase >> 10;
    const int srow0 = b << 10;

    ull acc2[TTG];
    float se[TTG];
#pragma unroll
    for (int t = 0; t < TTG; t++) { acc2[t] = 0ull; se[t] = 0.f; }

    for (int c = 0; c < 4; c++) {
        const int sloc0 = w * 128 + c * 32;

#pragma unroll
        for (int t = 0; t < TTG; t++) {
            float e = __expf(scores[(size_t)(tbase + t) * SS + sloc0 + lane]);
            se[t] += e;
            sh[w][lane * TTG + t] = pack2(e, e);
        }
        __syncwarp();

#pragma unroll 4
        for (int j = 0; j < 32; j += 8) {
            ull v[8];
#pragma unroll
            for (int k = 0; k < 8; k++)
                v[k] = *(const ull*)(g_s_ad + (size_t)(srow0 + sloc0 + j + k) * H + 2 * lane);
#pragma unroll
            for (int k = 0; k < 8; k++) {
                const ulonglong2* ep = (const ulonglong2*)&sh[w][(j + k) * TTG];
                ulonglong2 e01 = ep[0], e23 = ep[1], e45 = ep[2], e67 = ep[3];
                acc2[0] = fma2(v[k], e01.x, acc2[0]);
                acc2[1] = fma2(v[k], e01.y, acc2[1]);
                acc2[2] = fma2(v[k], e23.x, acc2[2]);
                acc2[3] = fma2(v[k], e23.y, acc2[3]);
                acc2[4] = fma2(v[k], e45.x, acc2[4]);
                acc2[5] = fma2(v[k], e45.y, acc2[5]);
                acc2[6] = fma2(v[k], e67.x, acc2[6]);
                acc2[7] = fma2(v[k], e67.y, acc2[7]);
            }
        }
        __syncwarp();
    }

#pragma unroll
    for (int t = 0; t < TTG; t++) {
        float s = se[t];
#pragma unroll
        for (int o = 16; o; o >>= 1) s += __shfl_xor_sync(~0u, s, o);
        if (lane == 0) sums_sh[w][t] = s;
    }

    // red union write — warp w's red region (TTG*H*4B = 2KB) == warp w's e2 region (2KB)
    float* red = (float*)sh;
#pragma unroll
    for (int t = 0; t < TTG; t++)
        *(ull*)&red[(w * TTG + t) * H + 2 * lane] = acc2[t];
    __syncthreads();

    // combine: 256 threads over 8 t × 32 h-pairs; thread -> (t = tid>>5, pair = tid&31)
    const int t = tid >> 5;
    const int hp = (tid & 31) * 2;
    float sx = 0.f, sy = 0.f;
#pragma unroll
    for (int ww = 0; ww < 8; ww++) {
        float2 p = unpack2(*(const ull*)&red[(ww * TTG + t) * H + hp]);
        sx += p.x; sy += p.y;
    }
    float sumexp = 0.f;
#pragma unroll
    for (int ww = 0; ww < 8; ww++) sumexp += sums_sh[ww][t];

    const int tg = tbase + t;
    const float rs = 1.f / sumexp;
    const float gt = g_gate[tg];
    const float2 ta = *(const float2*)&g_t_ad[(size_t)tg * H + hp];
    float2 o;
    o.x = ta.x * (1.f - gt) + sx * rs * gt;
    o.y = ta.y * (1.f - gt) + sy * rs * gt;
    *(float2*)&out_adapted[(size_t)tg * H + hp] = o;
}

// ---------------- launch ----------------
extern "C" void kernel_launch(void* const* d_in, const int* in_sizes, int n_in,
                              void* d_out, int out_size)
{
    (void)in_sizes; (void)n_in; (void)out_size;
    const float* src   = (const float*)d_in[0];
    const float* tgt   = (const float*)d_in[1];
    const float* sW1   = (const float*)d_in[2];
    const float* sb1   = (const float*)d_in[3];
    const float* sg    = (const float*)d_in[4];
    const float* sbeta = (const float*)d_in[5];
    const float* sW2   = (const float*)d_in[6];
    const float* sb2   = (const float*)d_in[7];
    const float* tW1   = (const float*)d_in[8];
    const float* tb1   = (const float*)d_in[9];
    const float* tg    = (const float*)d_in[10];
    const float* tbeta = (const float*)d_in[11];
    const float* tW2   = (const float*)d_in[12];
    const float* tb2   = (const float*)d_in[13];
    const float* cW    = (const float*)d_in[14];
    const float* cb    = (const float*)d_in[15];
    const float* cg    = (const float*)d_in[16];
    const float* cbeta = (const float*)d_in[17];
    const float* simW  = (const float*)d_in[18];
    const float* simb  = (const float*)d_in[19];

    float* out_adapted = (float*)d_out;                      // (B,T,H)
    float* out_scores  = out_adapted + (size_t)BB * TT * H;  // (B,T,S)

    cudaMemcpyToSymbolAsync(c_cg,   cg,    H * sizeof(float), 0, cudaMemcpyDeviceToDevice, 0);
    cudaMemcpyToSymbolAsync(c_cb,   cbeta, H * sizeof(float), 0, cudaMemcpyDeviceToDevice, 0);
    cudaMemcpyToSymbolAsync(c_w,    simW,  H * sizeof(float), 0, cudaMemcpyDeviceToDevice, 0);
    cudaMemcpyToSymbolAsync(c_simb, simb,  sizeof(float),     0, cudaMemcpyDeviceToDevice, 0);

    adapters_fused<<<BB * SS / 4 + BB * TT / 4, 256>>>(src, tgt,
                                                       sW1, sb1, sg, sbeta, sW2, sb2,
                                                       tW1, tb1, tg, tbeta, tW2, tb2,
                                                       cW, cb);
    score_kernel<<<(BB * TT) / TILE_T, 256>>>(out_scores);
    transfer_kernel<<<(BB * TT) / TTG, 256>>>(out_scores, out_adapted);
}

// round 16
// speedup vs baseline: 1.0631x; 1.0421x over previous
#include <cuda_runtime.h>
#include <math.h>

#define BB 2
#define SS 1024
#define TT 1024
#define DS 128
#define DT 64
#define H 64
#define LN_EPS 1e-5f

#define TILE_T 8
#define CH 32
#define USTRIDE 68   // floats; 272B row stride, 16B-aligned, conflict-free 16B reads
#define TTG 8        // t-rows per transfer block

typedef unsigned long long ull;

__device__ __forceinline__ ull fma2(ull a, ull b, ull c) {
    ull d; asm("fma.rn.f32x2 %0,%1,%2,%3;" : "=l"(d) : "l"(a), "l"(b), "l"(c)); return d;
}
__device__ __forceinline__ ull add2(ull a, ull b) {
    ull d; asm("add.rn.f32x2 %0,%1,%2;" : "=l"(d) : "l"(a), "l"(b)); return d;
}
__device__ __forceinline__ ull pack2(float lo, float hi) {
    ull d; asm("mov.b64 %0,{%1,%2};" : "=l"(d) : "f"(lo), "f"(hi)); return d;
}
__device__ __forceinline__ float2 unpack2(ull v) {
    float2 r; asm("mov.b64 {%0,%1},%2;" : "=f"(r.x), "=f"(r.y) : "l"(v)); return r;
}
__device__ __forceinline__ void cp16(void* smem_dst, const void* gsrc) {
    unsigned sa = (unsigned)__cvta_generic_to_shared(smem_dst);
    asm volatile("cp.async.cg.shared.global [%0], [%1], 16;" :: "r"(sa), "l"(gsrc));
}

// ---------------- scratch ----------------
__device__ float g_s_ad[BB * SS * H];
__device__ float g_u[BB * SS * H];
__device__ float g_t_ad[BB * TT * H];
__device__ float g_a[BB * TT * H];
__device__ float g_sum_u[BB * SS];
__device__ float g_su2[BB * SS];
__device__ float g_sum_a[BB * TT];
__device__ float g_sa2[BB * TT];
__device__ float g_gate[BB * TT];

// constants for score kernel (LDC.128 path)
__constant__ __align__(16) float c_cg[H];
__constant__ __align__(16) float c_cb[H];
__constant__ __align__(16) float c_w[H];
__constant__ float c_simb[1];

// ---------------- adapter body: 1 warp per row, 2 outputs/thread via LDG.64 ----------------
// Halves the LDG instruction count (the LSU dispatch floor that bound the old version).
// No block barriers: row state is warp-private (__syncwarp only).
template <int DIN, bool IS_TARGET>
__device__ __forceinline__ void adapter_row(
    int row, int tj,
    const float* __restrict__ X,
    const float* __restrict__ W1, const float* __restrict__ b1,
    const float* __restrict__ g,  const float* __restrict__ beta,
    const float* __restrict__ W2, const float* __restrict__ b2,
    const float* __restrict__ cWpart, const float* __restrict__ cb,
    float* sx, float* sr, float* sa)
{
    const int j2 = 2 * tj;

    // stage x row (warp-private smem)
    if (DIN == 128) ((float4*)sx)[tj] = ((const float4*)(X + (size_t)row * DIN))[tj];
    else            ((float2*)sx)[tj] = ((const float2*)(X + (size_t)row * DIN))[tj];
    __syncwarp();

    // layer 1: h[j2], h[j2+1] ; 1 LDG.64 per k (2 MACs)
    ull h2a = 0ull, h2b = 0ull;
#pragma unroll
    for (int k = 0; k < DIN; k += 2) {
        ull w0 = *(const ull*)&W1[(size_t)(k)     * H + j2];
        ull w1 = *(const ull*)&W1[(size_t)(k + 1) * H + j2];
        h2a = fma2(pack2(sx[k],     sx[k]),     w0, h2a);
        h2b = fma2(pack2(sx[k + 1], sx[k + 1]), w1, h2b);
    }
    float2 h = unpack2(add2(h2a, h2b));
    {
        float2 bv = *(const float2*)&b1[j2];
        h.x += bv.x; h.y += bv.y;
    }

    // LN stats: 32-lane shuffle reduce over 64 values (2 per lane)
    float s1 = h.x + h.y, s2 = h.x * h.x + h.y * h.y;
#pragma unroll
    for (int o = 16; o; o >>= 1) {
        s1 += __shfl_xor_sync(~0u, s1, o);
        s2 += __shfl_xor_sync(~0u, s2, o);
    }
    const float m   = s1 * (1.f / H);
    const float e2  = s2 * (1.f / H);
    const float inv = rsqrtf(e2 - m * m + LN_EPS);
    {
        float2 gv  = *(const float2*)&g[j2];
        float2 bev = *(const float2*)&beta[j2];
        float r0 = fmaxf((h.x - m) * inv * gv.x + bev.x, 0.f);
        float r1 = fmaxf((h.y - m) * inv * gv.y + bev.y, 0.f);
        *(float2*)&sr[j2] = make_float2(r0, r1);
    }
    __syncwarp();

    // layer 2
    ull a2a = 0ull, a2b = 0ull;
#pragma unroll
    for (int k = 0; k < H; k += 2) {
        ull w0 = *(const ull*)&W2[(size_t)(k)     * H + j2];
        ull w1 = *(const ull*)&W2[(size_t)(k + 1) * H + j2];
        a2a = fma2(pack2(sr[k],     sr[k]),     w0, a2a);
        a2b = fma2(pack2(sr[k + 1], sr[k + 1]), w1, a2b);
    }
    float2 ad = unpack2(add2(a2a, a2b));
    {
        float2 bv = *(const float2*)&b2[j2];
        ad.x += bv.x; ad.y += bv.y;
    }

    // store adapter output
    if (IS_TARGET) *(float2*)&g_t_ad[(size_t)row * H + j2] = ad;
    else           *(float2*)&g_s_ad[(size_t)row * H + j2] = ad;
    *(float2*)&sa[j2] = ad;

    if (IS_TARGET) {
        float s = ad.x + ad.y;
#pragma unroll
        for (int o = 16; o; o >>= 1) s += __shfl_xor_sync(~0u, s, o);
        if (tj == 0) g_gate[row] = 1.f / (1.f + __expf(-s * (1.f / H)));
    }
    __syncwarp();

    // projection: p = ad @ cWpart (+cb if target)
    ull p2a, p2b = 0ull;
    if (IS_TARGET) { float2 cbv = *(const float2*)&cb[j2]; p2a = pack2(cbv.x, cbv.y); }
    else           p2a = 0ull;
#pragma unroll
    for (int k = 0; k < H; k += 2) {
        ull w0 = *(const ull*)&cWpart[(size_t)(k)     * H + j2];
        ull w1 = *(const ull*)&cWpart[(size_t)(k + 1) * H + j2];
        p2a = fma2(pack2(sa[k],     sa[k]),     w0, p2a);
        p2b = fma2(pack2(sa[k + 1], sa[k + 1]), w1, p2b);
    }
    float2 p = unpack2(add2(p2a, p2b));

    if (IS_TARGET) *(float2*)&g_a[(size_t)row * H + j2] = p;
    else           *(float2*)&g_u[(size_t)row * H + j2] = p;

    float q1 = p.x + p.y, q2 = p.x * p.x + p.y * p.y;
#pragma unroll
    for (int o = 16; o; o >>= 1) {
        q1 += __shfl_xor_sync(~0u, q1, o);
        q2 += __shfl_xor_sync(~0u, q2, o);
    }
    if (tj == 0) {
        if (IS_TARGET) { g_sum_a[row] = q1; g_sa2[row] = q2; }
        else           { g_sum_u[row] = q1; g_su2[row] = q2; }
    }
}

// ---------------- fused adapters: 8 rows (8 warps) per 256-thread block ----------------
__global__ __launch_bounds__(256)
void adapters_fused(const float* __restrict__ src, const float* __restrict__ tgt,
                    const float* __restrict__ sW1, const float* __restrict__ sb1,
                    const float* __restrict__ sg,  const float* __restrict__ sbeta,
                    const float* __restrict__ sW2, const float* __restrict__ sb2,
                    const float* __restrict__ tW1, const float* __restrict__ tb1,
                    const float* __restrict__ tgam, const float* __restrict__ tbeta,
                    const float* __restrict__ tW2, const float* __restrict__ tb2,
                    const float* __restrict__ cW,  const float* __restrict__ cb)
{
    __shared__ __align__(16) float sh_x[8][DS];
    __shared__ __align__(16) float sh_r[8][H];
    __shared__ __align__(16) float sh_ad[8][H];

    const int rid = threadIdx.x >> 5;   // warp = row
    const int tj  = threadIdx.x & 31;
    const int SRC_BLOCKS = BB * SS / 8;

    if (blockIdx.x < SRC_BLOCKS) {
        int row = blockIdx.x * 8 + rid;
        adapter_row<DS, false>(row, tj, src, sW1, sb1, sg, sbeta, sW2, sb2,
                               cW + H * H, nullptr,
                               sh_x[rid], sh_r[rid], sh_ad[rid]);
    } else {
        int row = (blockIdx.x - SRC_BLOCKS) * 8 + rid;
        adapter_row<DT, true>(row, tj, tgt, tW1, tb1, tgam, tbeta, tW2, tb2,
                              cW, cb,
                              sh_x[rid], sh_r[rid], sh_ad[rid]);
    }
}

// ---------------- score kernel: CH=32, 3-buffer ring (R12 exact, proven) ----------------
__global__ __launch_bounds__(256, 2)
void score_kernel(float* __restrict__ out_scores)
{
    __shared__ __align__(16) float u_sh[3][CH * USTRIDE];
    __shared__ __align__(16) float a_sh[TILE_T][H];

    const int tid = threadIdx.x;
    const int lane = tid & 31;
    const int w = tid >> 5;
    const int tglob = blockIdx.x * TILE_T + w;
    const int b = tglob >> 10;
    const int srow0 = b << 10;

    ((float2*)a_sh[w])[lane] = ((const float2*)(g_a + (size_t)tglob * H))[lane];

    const float suma = g_sum_a[tglob];
    const float sqa  = g_sa2[tglob];
    const float simb0 = c_simb[0];

    {
        const float4* src = (const float4*)(g_u + (size_t)srow0 * H);
#pragma unroll
        for (int rep = 0; rep < 2; rep++) {
            int f = tid + rep * 256;
            int r = f >> 4, q = f & 15;
            cp16(&u_sh[0][r * USTRIDE + q * 4], src + f);
        }
        asm volatile("cp.async.commit_group;");
    }

    float* srow_out = out_scores + (size_t)tglob * SS;

    int buf = 0;
    for (int c = 0; c < SS / CH; c++) {
        if (c < SS / CH - 1) {
            const float4* src = (const float4*)(g_u + (size_t)(srow0 + (c + 1) * CH) * H);
            float* dst = u_sh[(buf + 1) % 3];
#pragma unroll
            for (int rep = 0; rep < 2; rep++) {
                int f = tid + rep * 256;
                int r = f >> 4, q = f & 15;
                cp16(&dst[r * USTRIDE + q * 4], src + f);
            }
            asm volatile("cp.async.commit_group;");
            asm volatile("cp.async.wait_group 1;");
        } else {
            asm volatile("cp.async.wait_group 0;");
        }
        __syncthreads();

        const ulonglong2* up2 = (const ulonglong2*)&u_sh[buf][lane * USTRIDE];
        ull u2[H / 2];
#pragma unroll
        for (int i = 0; i < H / 4; i++) {
            ulonglong2 v = up2[i];
            u2[2 * i] = v.x; u2[2 * i + 1] = v.y;
        }

        const int sidx = srow0 + c * CH + lane;
        const float su  = g_sum_u[sidx];
        const float squ = g_su2[sidx];

        const ulonglong2* ap2 = (const ulonglong2*)a_sh[w];

        ull d0 = 0ull, d1 = 0ull, d2 = 0ull, d3 = 0ull;
#pragma unroll
        for (int i = 0; i < H / 4; i += 2) {
            ulonglong2 aa = ap2[i];
            ulonglong2 ab = ap2[i + 1];
            d0 = fma2(aa.x, u2[2 * i],     d0);
            d1 = fma2(aa.y, u2[2 * i + 1], d1);
            d2 = fma2(ab.x, u2[2 * i + 2], d2);
            d3 = fma2(ab.y, u2[2 * i + 3], d3);
        }
        float2 f0 = unpack2(d0), f1 = unpack2(d1), f2 = unpack2(d2), f3 = unpack2(d3);
        const float dot = ((f0.x + f0.y) + (f1.x + f1.y)) + ((f2.x + f2.y) + (f3.x + f3.y));

        const float m   = (suma + su) * (1.f / H);
        const float e2  = (sqa + 2.f * dot + squ) * (1.f / H);
        const float inv = rsqrtf(e2 - m * m + LN_EPS);
        const float nm  = -m * inv;
        const ull inv2 = pack2(inv, inv);
        const ull nm2  = pack2(nm, nm);

        ull acca = 0ull, accb = 0ull;
#pragma unroll
        for (int i = 0; i < H / 4; i++) {
            ulonglong2 aa  = ap2[i];
            ulonglong2 kcg = *(const ulonglong2*)&c_cg[4 * i];
            ulonglong2 kcb = *(const ulonglong2*)&c_cb[4 * i];
            ulonglong2 kw  = *(const ulonglong2*)&c_w[4 * i];
            ull p0 = add2(aa.x, u2[2 * i]);
            ull p1 = add2(aa.y, u2[2 * i + 1]);
            ull z0 = fma2(p0, inv2, nm2);
            ull z1 = fma2(p1, inv2, nm2);
            ull y0 = fma2(z0, kcg.x, kcb.x);
            ull y1 = fma2(z1, kcg.y, kcb.y);
            float2 ya = unpack2(y0), yb = unpack2(y1);
            ya.x = fmaxf(ya.x, 0.f); ya.y = fmaxf(ya.y, 0.f);
            yb.x = fmaxf(yb.x, 0.f); yb.y = fmaxf(yb.y, 0.f);
            acca = fma2(pack2(ya.x, ya.y), kw.x, acca);
            accb = fma2(pack2(yb.x, yb.y), kw.y, accb);
        }
        float2 sa2 = unpack2(acca), sb2 = unpack2(accb);
        const float acc = (sa2.x + sa2.y) + (sb2.x + sb2.y);
        const float score = 1.f / (1.f + __expf(-(acc + simb0)));
        srow_out[c * CH + lane] = score;

        buf = (buf + 1) % 3;
    }
}

// ---------------- transfer: 256 thr / 8 warps, TTG=8; e2/red smem UNION (16KB) ----------
__global__ __launch_bounds__(256)
void transfer_kernel(const float* __restrict__ scores, float* __restrict__ out_adapted)
{
    __shared__ __align__(16) ull sh[8][32 * TTG];   // 16KB; e2 view phase1, red view phase2
    __shared__ float sums_sh[8][TTG];

    const int tid = threadIdx.x;
    const int w = tid >> 5, lane = tid & 31;
    const int tbase = blockIdx.x * TTG;
    const int b = tbase >> 10;
    const int srow0 = b << 10;

    ull acc2[TTG];
    float se[TTG];
#pragma unroll
    for (int t = 0; t < TTG; t++) { acc2[t] = 0ull; se[t] = 0.f; }

    for (int c = 0; c < 4; c++) {
        const int sloc0 = w * 128 + c * 32;

#pragma unroll
        for (int t = 0; t < TTG; t++) {
            float e = __expf(scores[(size_t)(tbase + t) * SS + sloc0 + lane]);
            se[t] += e;
            sh[w][lane * TTG + t] = pack2(e, e);
        }
        __syncwarp();

#pragma unroll 4
        for (int j = 0; j < 32; j += 8) {
            ull v[8];
#pragma unroll
            for (int k = 0; k < 8; k++)
                v[k] = *(const ull*)(g_s_ad + (size_t)(srow0 + sloc0 + j + k) * H + 2 * lane);
#pragma unroll
            for (int k = 0; k < 8; k++) {
                const ulonglong2* ep = (const ulonglong2*)&sh[w][(j + k) * TTG];
                ulonglong2 e01 = ep[0], e23 = ep[1], e45 = ep[2], e67 = ep[3];
                acc2[0] = fma2(v[k], e01.x, acc2[0]);
                acc2[1] = fma2(v[k], e01.y, acc2[1]);
                acc2[2] = fma2(v[k], e23.x, acc2[2]);
                acc2[3] = fma2(v[k], e23.y, acc2[3]);
                acc2[4] = fma2(v[k], e45.x, acc2[4]);
                acc2[5] = fma2(v[k], e45.y, acc2[5]);
                acc2[6] = fma2(v[k], e67.x, acc2[6]);
                acc2[7] = fma2(v[k], e67.y, acc2[7]);
            }
        }
        __syncwarp();
    }

#pragma unroll
    for (int t = 0; t < TTG; t++) {
        float s = se[t];
#pragma unroll
        for (int o = 16; o; o >>= 1) s += __shfl_xor_sync(~0u, s, o);
        if (lane == 0) sums_sh[w][t] = s;
    }

    float* red = (float*)sh;
#pragma unroll
    for (int t = 0; t < TTG; t++)
        *(ull*)&red[(w * TTG + t) * H + 2 * lane] = acc2[t];
    __syncthreads();

    const int t = tid >> 5;
    const int hp = (tid & 31) * 2;
    float sx = 0.f, sy = 0.f;
#pragma unroll
    for (int ww = 0; ww < 8; ww++) {
        float2 p = unpack2(*(const ull*)&red[(ww * TTG + t) * H + hp]);
        sx += p.x; sy += p.y;
    }
    float sumexp = 0.f;
#pragma unroll
    for (int ww = 0; ww < 8; ww++) sumexp += sums_sh[ww][t];

    const int tg = tbase + t;
    const float rs = 1.f / sumexp;
    const float gt = g_gate[tg];
    const float2 ta = *(const float2*)&g_t_ad[(size_t)tg * H + hp];
    float2 o;
    o.x = ta.x * (1.f - gt) + sx * rs * gt;
    o.y = ta.y * (1.f - gt) + sy * rs * gt;
    *(float2*)&out_adapted[(size_t)tg * H + hp] = o;
}

// ---------------- launch ----------------
extern "C" void kernel_launch(void* const* d_in, const int* in_sizes, int n_in,
                              void* d_out, int out_size)
{
    (void)in_sizes; (void)n_in; (void)out_size;
    const float* src   = (const float*)d_in[0];
    const float* tgt   = (const float*)d_in[1];
    const float* sW1   = (const float*)d_in[2];
    const float* sb1   = (const float*)d_in[3];
    const float* sg    = (const float*)d_in[4];
    const float* sbeta = (const float*)d_in[5];
    const float* sW2   = (const float*)d_in[6];
    const float* sb2   = (const float*)d_in[7];
    const float* tW1   = (const float*)d_in[8];
    const float* tb1   = (const float*)d_in[9];
    const float* tg    = (const float*)d_in[10];
    const float* tbeta = (const float*)d_in[11];
    const float* tW2   = (const float*)d_in[12];
    const float* tb2   = (const float*)d_in[13];
    const float* cW    = (const float*)d_in[14];
    const float* cb    = (const float*)d_in[15];
    const float* cg    = (const float*)d_in[16];
    const float* cbeta = (const float*)d_in[17];
    const float* simW  = (const float*)d_in[18];
    const float* simb  = (const float*)d_in[19];

    float* out_adapted = (float*)d_out;                      // (B,T,H)
    float* out_scores  = out_adapted + (size_t)BB * TT * H;  // (B,T,S)

    cudaMemcpyToSymbolAsync(c_cg,   cg,    H * sizeof(float), 0, cudaMemcpyDeviceToDevice, 0);
    cudaMemcpyToSymbolAsync(c_cb,   cbeta, H * sizeof(float), 0, cudaMemcpyDeviceToDevice, 0);
    cudaMemcpyToSymbolAsync(c_w,    simW,  H * sizeof(float), 0, cudaMemcpyDeviceToDevice, 0);
    cudaMemcpyToSymbolAsync(c_simb, simb,  sizeof(float),     0, cudaMemcpyDeviceToDevice, 0);

    adapters_fused<<<BB * SS / 8 + BB * TT / 8, 256>>>(src, tgt,
                                                       sW1, sb1, sg, sbeta, sW2, sb2,
                                                       tW1, tb1, tg, tbeta, tW2, tb2,
                                                       cW, cb);
    score_kernel<<<(BB * TT) / TILE_T, 256>>>(out_scores);
    transfer_kernel<<<(BB * TT) / TTG, 256>>>(out_scores, out_adapted);
}